// round 15
// baseline (speedup 1.0000x reference)
#include <cuda_runtime.h>
#include <cuda_fp16.h>
#include <cstdint>

// ---------------------------------------------------------------------------
// Problem shape
// ---------------------------------------------------------------------------
constexpr int NB = 4, NS = 4096, ND = 256;
constexpr int NSEQ = NB * NS;

// ---------------------------------------------------------------------------
// Flash tiling: QR=64, 4 warps, 2 CTAs/SM. Distance-2 fragment prefetch
// (3-deep buffers) in QK and PV; PV fragments preloaded under the softmax
// converts. K,V double-buffered; ONE barrier per key-block.
// ---------------------------------------------------------------------------
constexpr int QR   = 64;
constexpr int FTH  = 128;
constexpr int KC   = 32;
constexpr int PAD  = 264;             // fp16 elems per smem row (256 + 8)
constexpr int NBLK = NS / KC;         // 128

constexpr int TILE_Q = QR * PAD * 2;        // 33792
constexpr int TILE_K = KC * PAD * 2;        // 16896
constexpr int F_QH = 0;
constexpr int F_K0 = F_QH + TILE_Q;
constexpr int F_K1 = F_K0 + TILE_K;
constexpr int F_V0 = F_K1 + TILE_K;
constexpr int F_V1 = F_V0 + TILE_K;
constexpr int F_SMEM = F_V1 + TILE_K;       // 101376 (x2 CTAs < 227KB)

// projection GEMM tiling — single-pass fp16
constexpr int BM = 128, BN = 128, BK = 32;
constexpr int A_PAD  = 40;
constexpr int OFF_A  = 0;
constexpr int OFF_B  = BM * A_PAD * 2;      // 10240
constexpr int P_STG  = 2 * BM * A_PAD * 2;  // 20480
constexpr int P_SMEM = 2 * P_STG;           // 40960

constexpr float QSCALE = 1.4426950408889634f / 16.0f;

// ---------------------------------------------------------------------------
// Scratch (device globals; allocation-free)
// ---------------------------------------------------------------------------
#define DEVARR __device__ __align__(256)
DEVARR __half g_qh[(size_t)NSEQ * ND];
DEVARR __half g_kh[(size_t)NSEQ * ND];
DEVARR __half g_vh[(size_t)NSEQ * ND];

// ---------------------------------------------------------------------------
// PTX helpers (plain-sm_100-legal)
// ---------------------------------------------------------------------------
__device__ __forceinline__ uint32_t s2u(const void* p) {
    return (uint32_t)__cvta_generic_to_shared(p);
}
__device__ __forceinline__ void ldm4(uint32_t* r, uint32_t a) {
    asm volatile("ldmatrix.sync.aligned.m8n8.x4.shared.b16 {%0,%1,%2,%3},[%4];"
                 : "=r"(r[0]), "=r"(r[1]), "=r"(r[2]), "=r"(r[3]) : "r"(a));
}
__device__ __forceinline__ void ldm4t(uint32_t* r, uint32_t a) {
    asm volatile("ldmatrix.sync.aligned.m8n8.x4.trans.shared.b16 {%0,%1,%2,%3},[%4];"
                 : "=r"(r[0]), "=r"(r[1]), "=r"(r[2]), "=r"(r[3]) : "r"(a));
}
__device__ __forceinline__ void mma_f16(float* c, const uint32_t* a,
                                        uint32_t b0, uint32_t b1) {
    asm volatile(
        "mma.sync.aligned.m16n8k16.row.col.f32.f16.f16.f32 "
        "{%0,%1,%2,%3},{%4,%5,%6,%7},{%8,%9},{%0,%1,%2,%3};"
        : "+f"(c[0]), "+f"(c[1]), "+f"(c[2]), "+f"(c[3])
        : "r"(a[0]), "r"(a[1]), "r"(a[2]), "r"(a[3]), "r"(b0), "r"(b1));
}
__device__ __forceinline__ void cp16(uint32_t dst, const void* src) {
    asm volatile("cp.async.cg.shared.global [%0],[%1],16;" :: "r"(dst), "l"(src));
}
__device__ __forceinline__ void cp_commit() {
    asm volatile("cp.async.commit_group;" ::: "memory");
}
template <int N>
__device__ __forceinline__ void cp_wait() {
    asm volatile("cp.async.wait_group %0;" :: "n"(N) : "memory");
}
__device__ __forceinline__ float ex2(float x) {
    float y; asm("ex2.approx.f32 %0,%1;" : "=f"(y) : "f"(x)); return y;
}
__device__ __forceinline__ uint32_t h2bits(__half2 h) {
    uint32_t u; *(__half2*)&u = h; return u;
}

// ---------------------------------------------------------------------------
// Fused QKV projection, single-pass fp16: grid (N/BN, M/BM, 3).
// C = scale * (x[M,K] @ W[N,K]^T), inputs rounded to fp16 at staging.
// ---------------------------------------------------------------------------
__global__ __launch_bounds__(256, 1) void proj_qkv(
    const float* __restrict__ x,
    const float* __restrict__ Wq, const float* __restrict__ Wk,
    const float* __restrict__ Wv,
    __half* __restrict__ Qh, __half* __restrict__ Kh, __half* __restrict__ Vh)
{
    extern __shared__ char sm[];
    const int z = blockIdx.z;
    const float* B = (z == 0) ? Wq : (z == 1) ? Wk : Wv;
    __half* Ch = (z == 0) ? Qh : (z == 1) ? Kh : Vh;
    const float scale = (z == 0) ? QSCALE : 1.0f;
    const int N = ND, K = ND;

    const int t = threadIdx.x, lane = t & 31, wid = t >> 5;
    const int wm = wid >> 2, wn = wid & 3;
    const int row0 = blockIdx.y * BM, col0 = blockIdx.x * BN;
    const int ar = t >> 1, ac = (t & 1) * 16;
    const uint32_t smb = s2u(sm);

    float4 ra[4], rb[4];
    float acc[4][4][4];
    #pragma unroll
    for (int i = 0; i < 4; i++)
        #pragma unroll
        for (int j = 0; j < 4; j++)
            #pragma unroll
            for (int e = 0; e < 4; e++) acc[i][j][e] = 0.f;

    auto gload = [&](int kt) {
        const float* ap = x + (size_t)(row0 + ar) * K + kt * BK + ac;
        const float* bp = B + (size_t)(col0 + ar) * K + kt * BK + ac;
        #pragma unroll
        for (int i = 0; i < 4; i++) ra[i] = *(const float4*)(ap + 4 * i);
        #pragma unroll
        for (int i = 0; i < 4; i++) rb[i] = *(const float4*)(bp + 4 * i);
    };
    auto sstore = [&](int buf) {
        char* s0 = sm + buf * P_STG;
        #pragma unroll
        for (int i = 0; i < 4; i++) {
            uint2 h;
            h.x = h2bits(__floats2half2_rn(ra[i].x, ra[i].y));
            h.y = h2bits(__floats2half2_rn(ra[i].z, ra[i].w));
            *(uint2*)(s0 + OFF_A + (ar * A_PAD + ac + 4 * i) * 2) = h;
        }
        #pragma unroll
        for (int i = 0; i < 4; i++) {
            uint2 h;
            h.x = h2bits(__floats2half2_rn(rb[i].x, rb[i].y));
            h.y = h2bits(__floats2half2_rn(rb[i].z, rb[i].w));
            *(uint2*)(s0 + OFF_B + (ar * A_PAD + ac + 4 * i) * 2) = h;
        }
    };
    auto compute = [&](int buf) {
        uint32_t sb = smb + buf * P_STG;
        #pragma unroll
        for (int ks = 0; ks < 2; ks++) {
            uint32_t ah[4][4];
            #pragma unroll
            for (int mi = 0; mi < 4; mi++) {
                int row = wm * 64 + mi * 16 + (lane & 15);
                int col = ks * 16 + (lane >> 4) * 8;
                ldm4(ah[mi], sb + OFF_A + (uint32_t)(row * A_PAD + col) * 2);
            }
            uint32_t bh[2][4];
            #pragma unroll
            for (int ni = 0; ni < 2; ni++) {
                int row = wn * 32 + ni * 16 + (lane & 15);
                int col = ks * 16 + (lane >> 4) * 8;
                ldm4(bh[ni], sb + OFF_B + (uint32_t)(row * A_PAD + col) * 2);
            }
            #pragma unroll
            for (int mi = 0; mi < 4; mi++)
                #pragma unroll
                for (int j = 0; j < 4; j++) {
                    int ni = j >> 1, sbb = j & 1;
                    mma_f16(acc[mi][j], ah[mi], bh[ni][sbb], bh[ni][sbb + 2]);
                }
        }
    };

    const int KT = K / BK;
    gload(0); sstore(0); __syncthreads();
    for (int kt = 0; kt < KT; kt++) {
        if (kt + 1 < KT) gload(kt + 1);
        compute(kt & 1);
        __syncthreads();
        if (kt + 1 < KT) { sstore((kt + 1) & 1); __syncthreads(); }
    }

    #pragma unroll
    for (int mi = 0; mi < 4; mi++)
        #pragma unroll
        for (int j = 0; j < 4; j++) {
            const float* c = acc[mi][j];
            int r  = row0 + wm * 64 + mi * 16 + (lane >> 2);
            int cc = col0 + wn * 32 + j * 8 + (lane & 3) * 2;
            #pragma unroll
            for (int hrow = 0; hrow < 2; hrow++) {
                float v0 = c[hrow * 2 + 0] * scale;
                float v1 = c[hrow * 2 + 1] * scale;
                size_t idx = (size_t)(r + hrow * 8) * N + cc;
                *(uint32_t*)&Ch[idx] = h2bits(__floats2half2_rn(v0, v1));
            }
        }
}

// ---------------------------------------------------------------------------
// Fused flash attention: distance-2 fragment prefetch in all MMA loops;
// PV fragments preloaded under the softmax converts.
// All operands single fp16; no-max softmax (scores bounded); row-sum deferred.
// K,V double-buffered, ONE barrier per key-block. grid (NS/QR, NB).
// ---------------------------------------------------------------------------
__global__ __launch_bounds__(FTH, 2) void flash(
    const __half* __restrict__ Qh, const __half* __restrict__ Kh,
    const __half* __restrict__ Vh, float* __restrict__ O)
{
    extern __shared__ char sm[];
    const uint32_t smb = s2u(sm);
    const int t = threadIdx.x, lane = t & 31, w = t >> 5;
    const int b = blockIdx.y, q0 = blockIdx.x * QR;

    const size_t qbase = ((size_t)b * NS + q0) * ND;
    const size_t kvb   = (size_t)b * NS * ND;

    auto loadQ = [&]() {
        for (int i = t; i < QR * 32; i += FTH) {
            int r = i >> 5, ch = i & 31;
            cp16(smb + F_QH + (uint32_t)(r * PAD * 2 + ch * 16),
                 Qh + qbase + (size_t)r * ND + ch * 8);
        }
    };
    auto loadKV = [&](int blk, int st) {
        size_t base = kvb + (size_t)blk * KC * ND;
        uint32_t kb = smb + (st ? F_K1 : F_K0);
        uint32_t vb = smb + (st ? F_V1 : F_V0);
        for (int i = t; i < KC * 32; i += FTH) {
            int r = i >> 5, ch = i & 31;
            uint32_t d = (uint32_t)(r * PAD * 2 + ch * 16);
            cp16(kb + d, Kh + base + (size_t)r * ND + ch * 8);
            cp16(vb + d, Vh + base + (size_t)r * ND + ch * 8);
        }
    };

    loadQ(); loadKV(0, 0); cp_commit();

    float o[32][4];
    #pragma unroll
    for (int g = 0; g < 32; g++)
        #pragma unroll
        for (int e = 0; e < 4; e++) o[g][e] = 0.f;
    float lsum0 = 0.f, lsum1 = 0.f;

    // hoisted row bases (bytes)
    const uint32_t qrow_off  = (uint32_t)((w * 16 + (lane & 15)) * PAD) * 2;
    const uint32_t row0_off  = (uint32_t)((lane & 15) * PAD) * 2;
    const uint32_t row1_off  = (uint32_t)((16 + (lane & 15)) * PAD) * 2;
    const uint32_t fcol_off  = (uint32_t)((lane >> 4) * 8) * 2;

    for (int blk = 0; blk < NBLK; blk++) {
        const int st = blk & 1;

        cp_wait<0>();
        __syncthreads();
        if (blk + 1 < NBLK) { loadKV(blk + 1, st ^ 1); cp_commit(); }

        const uint32_t kbase = smb + (st ? F_K1 : F_K0) + fcol_off;
        const uint32_t vbase = smb + (st ? F_V1 : F_V0) + fcol_off;
        const uint32_t qb    = smb + F_QH + qrow_off + fcol_off;

        // ---- QK^T (both key halves), distance-2 fragment prefetch ----
        float s[4][4];
        #pragma unroll
        for (int nj = 0; nj < 4; nj++)
            #pragma unroll
            for (int e = 0; e < 4; e++) s[nj][e] = 0.f;

        uint32_t qf[3][4], kf0[3][4], kf1[3][4];
        ldm4(qf[0],  qb);
        ldm4(kf0[0], kbase + row0_off);
        ldm4(kf1[0], kbase + row1_off);
        ldm4(qf[1],  qb + 32);
        ldm4(kf0[1], kbase + row0_off + 32);
        ldm4(kf1[1], kbase + row1_off + 32);
        #pragma unroll
        for (int k16 = 0; k16 < 16; k16++) {
            const int cur = k16 % 3;
            if (k16 < 14) {
                const int nl = (k16 + 2) % 3;
                const uint32_t c = (uint32_t)((k16 + 2) * 16) * 2;
                ldm4(qf[nl],  qb + c);
                ldm4(kf0[nl], kbase + row0_off + c);
                ldm4(kf1[nl], kbase + row1_off + c);
            }
            mma_f16(s[0], qf[cur], kf0[cur][0], kf0[cur][2]);
            mma_f16(s[1], qf[cur], kf0[cur][1], kf0[cur][3]);
            mma_f16(s[2], qf[cur], kf1[cur][0], kf1[cur][2]);
            mma_f16(s[3], qf[cur], kf1[cur][1], kf1[cur][3]);
        }

        uint32_t pah[2][4];

        // ---- preload PV-A frags, then convertA (LDS latency hidden) ----
        uint32_t vfa[3][4];
        ldm4t(vfa[0], vbase + row0_off);
        ldm4t(vfa[1], vbase + row0_off + 32);
        {
            s[0][0] = ex2(s[0][0]); lsum0 += s[0][0];
            s[0][1] = ex2(s[0][1]); lsum0 += s[0][1];
            s[0][2] = ex2(s[0][2]); lsum1 += s[0][2];
            s[0][3] = ex2(s[0][3]); lsum1 += s[0][3];
            s[1][0] = ex2(s[1][0]); lsum0 += s[1][0];
            s[1][1] = ex2(s[1][1]); lsum0 += s[1][1];
            s[1][2] = ex2(s[1][2]); lsum1 += s[1][2];
            s[1][3] = ex2(s[1][3]); lsum1 += s[1][3];
            pah[0][0] = h2bits(__floats2half2_rn(s[0][0], s[0][1]));
            pah[0][1] = h2bits(__floats2half2_rn(s[0][2], s[0][3]));
            pah[0][2] = h2bits(__floats2half2_rn(s[1][0], s[1][1]));
            pah[0][3] = h2bits(__floats2half2_rn(s[1][2], s[1][3]));
        }

        // ---- PV-A: o += pah[0] * V[rows 0..15], distance-2 prefetch ----
        #pragma unroll
        for (int g = 0; g < 16; g++) {
            const int cur = g % 3;
            if (g < 14) {
                const int nl = (g + 2) % 3;
                ldm4t(vfa[nl], vbase + row0_off + (uint32_t)((g + 2) * 16) * 2);
            }
            mma_f16(o[g * 2 + 0], pah[0], vfa[cur][0], vfa[cur][1]);
            mma_f16(o[g * 2 + 1], pah[0], vfa[cur][2], vfa[cur][3]);
        }

        // ---- preload PV-B frags, then convertB ----
        uint32_t vfb[3][4];
        ldm4t(vfb[0], vbase + row1_off);
        ldm4t(vfb[1], vbase + row1_off + 32);
        {
            s[2][0] = ex2(s[2][0]); lsum0 += s[2][0];
            s[2][1] = ex2(s[2][1]); lsum0 += s[2][1];
            s[2][2] = ex2(s[2][2]); lsum1 += s[2][2];
            s[2][3] = ex2(s[2][3]); lsum1 += s[2][3];
            s[3][0] = ex2(s[3][0]); lsum0 += s[3][0];
            s[3][1] = ex2(s[3][1]); lsum0 += s[3][1];
            s[3][2] = ex2(s[3][2]); lsum1 += s[3][2];
            s[3][3] = ex2(s[3][3]); lsum1 += s[3][3];
            pah[1][0] = h2bits(__floats2half2_rn(s[2][0], s[2][1]));
            pah[1][1] = h2bits(__floats2half2_rn(s[2][2], s[2][3]));
            pah[1][2] = h2bits(__floats2half2_rn(s[3][0], s[3][1]));
            pah[1][3] = h2bits(__floats2half2_rn(s[3][2], s[3][3]));
        }

        // ---- PV-B: o += pah[1] * V[rows 16..31], distance-2 prefetch ----
        #pragma unroll
        for (int g = 0; g < 16; g++) {
            const int cur = g % 3;
            if (g < 14) {
                const int nl = (g + 2) % 3;
                ldm4t(vfb[nl], vbase + row1_off + (uint32_t)((g + 2) * 16) * 2);
            }
            mma_f16(o[g * 2 + 0], pah[1], vfb[cur][0], vfb[cur][1]);
            mma_f16(o[g * 2 + 1], pah[1], vfb[cur][2], vfb[cur][3]);
        }
    }

    // ---- epilogue: reduce row sums across the lane quad, O /= l ----
    lsum0 += __shfl_xor_sync(0xffffffffu, lsum0, 1);
    lsum0 += __shfl_xor_sync(0xffffffffu, lsum0, 2);
    lsum1 += __shfl_xor_sync(0xffffffffu, lsum1, 1);
    lsum1 += __shfl_xor_sync(0xffffffffu, lsum1, 2);
    const float r0 = 1.f / lsum0, r1 = 1.f / lsum1;
    const int orow = q0 + w * 16 + (lane >> 2);
    const int ocol = (lane & 3) * 2;
    float* ob = O + ((size_t)b * NS) * ND;
    #pragma unroll
    for (int g = 0; g < 32; g++) {
        int cc = g * 8 + ocol;
        float2 v0 = {o[g][0] * r0, o[g][1] * r0};
        float2 v1 = {o[g][2] * r1, o[g][3] * r1};
        *(float2*)&ob[(size_t)orow * ND + cc]       = v0;
        *(float2*)&ob[(size_t)(orow + 8) * ND + cc] = v1;
    }
}

// ---------------------------------------------------------------------------
// Launch
// ---------------------------------------------------------------------------
extern "C" void kernel_launch(void* const* d_in, const int* in_sizes, int n_in,
                              void* d_out, int out_size)
{
    const float* x  = (const float*)d_in[0];
    const float* Wq = (const float*)d_in[1];
    const float* Wk = (const float*)d_in[2];
    const float* Wv = (const float*)d_in[3];
    float* out = (float*)d_out;

    __half *qh, *kh, *vh;
    cudaGetSymbolAddress((void**)&qh, g_qh);
    cudaGetSymbolAddress((void**)&kh, g_kh);
    cudaGetSymbolAddress((void**)&vh, g_vh);

    cudaFuncSetAttribute(proj_qkv, cudaFuncAttributeMaxDynamicSharedMemorySize, P_SMEM);
    cudaFuncSetAttribute(flash,    cudaFuncAttributeMaxDynamicSharedMemorySize, F_SMEM);

    {
        dim3 g(ND / BN, NSEQ / BM, 3);
        proj_qkv<<<g, 256, P_SMEM>>>(x, Wq, Wk, Wv, qh, kh, vh);
    }
    {
        dim3 g(NS / QR, NB);
        flash<<<g, FTH, F_SMEM>>>(qh, kh, vh, out);
    }
}

// round 17
// speedup vs baseline: 1.0049x; 1.0049x over previous
#include <cuda_runtime.h>
#include <cuda_fp16.h>
#include <cstdint>

// ---------------------------------------------------------------------------
// Problem shape
// ---------------------------------------------------------------------------
constexpr int NB = 4, NS = 4096, ND = 256;
constexpr int NSEQ = NB * NS;

// ---------------------------------------------------------------------------
// Flash tiling (R13/R15 proven structure + de-phase spin)
// ---------------------------------------------------------------------------
constexpr int QR   = 64;
constexpr int FTH  = 128;
constexpr int KC   = 32;
constexpr int PAD  = 264;             // fp16 elems per smem row (256 + 8)
constexpr int NBLK = NS / KC;         // 128

constexpr int TILE_Q = QR * PAD * 2;        // 33792
constexpr int TILE_K = KC * PAD * 2;        // 16896
constexpr int F_QH = 0;
constexpr int F_K0 = F_QH + TILE_Q;
constexpr int F_K1 = F_K0 + TILE_K;
constexpr int F_V0 = F_K1 + TILE_K;
constexpr int F_V1 = F_V0 + TILE_K;
constexpr int F_SMEM = F_V1 + TILE_K;       // 101376 (x2 CTAs < 227KB)

// fused projection tiling: BM=64 x-rows, BN=128 out-cols, BK=32, 8 warps,
// 3 weight planes staged; x read ONCE (was 3x across separate launches).
constexpr int PBM = 64, PBN = 128, PBK = 32;
constexpr int A_PAD  = 40;
constexpr int OFF_X  = 0;
constexpr int OFF_W  = PBM * A_PAD * 2;           // 5120
constexpr int W_PL   = PBN * A_PAD * 2;           // 10240 per weight
constexpr int P_STG  = OFF_W + 3 * W_PL;          // 35840
constexpr int P_SMEM = 2 * P_STG;                 // 71680

constexpr float QSCALE = 1.4426950408889634f / 16.0f;

// ---------------------------------------------------------------------------
// Scratch (device globals; allocation-free)
// ---------------------------------------------------------------------------
#define DEVARR __device__ __align__(256)
DEVARR __half g_qh[(size_t)NSEQ * ND];
DEVARR __half g_kh[(size_t)NSEQ * ND];
DEVARR __half g_vh[(size_t)NSEQ * ND];

// ---------------------------------------------------------------------------
// PTX helpers (plain-sm_100-legal)
// ---------------------------------------------------------------------------
__device__ __forceinline__ uint32_t s2u(const void* p) {
    return (uint32_t)__cvta_generic_to_shared(p);
}
__device__ __forceinline__ void ldm4(uint32_t* r, uint32_t a) {
    asm volatile("ldmatrix.sync.aligned.m8n8.x4.shared.b16 {%0,%1,%2,%3},[%4];"
                 : "=r"(r[0]), "=r"(r[1]), "=r"(r[2]), "=r"(r[3]) : "r"(a));
}
__device__ __forceinline__ void ldm4t(uint32_t* r, uint32_t a) {
    asm volatile("ldmatrix.sync.aligned.m8n8.x4.trans.shared.b16 {%0,%1,%2,%3},[%4];"
                 : "=r"(r[0]), "=r"(r[1]), "=r"(r[2]), "=r"(r[3]) : "r"(a));
}
__device__ __forceinline__ void mma_f16(float* c, const uint32_t* a,
                                        uint32_t b0, uint32_t b1) {
    asm volatile(
        "mma.sync.aligned.m16n8k16.row.col.f32.f16.f16.f32 "
        "{%0,%1,%2,%3},{%4,%5,%6,%7},{%8,%9},{%0,%1,%2,%3};"
        : "+f"(c[0]), "+f"(c[1]), "+f"(c[2]), "+f"(c[3])
        : "r"(a[0]), "r"(a[1]), "r"(a[2]), "r"(a[3]), "r"(b0), "r"(b1));
}
__device__ __forceinline__ void cp16(uint32_t dst, const void* src) {
    asm volatile("cp.async.cg.shared.global [%0],[%1],16;" :: "r"(dst), "l"(src));
}
__device__ __forceinline__ void cp_commit() {
    asm volatile("cp.async.commit_group;" ::: "memory");
}
template <int N>
__device__ __forceinline__ void cp_wait() {
    asm volatile("cp.async.wait_group %0;" :: "n"(N) : "memory");
}
__device__ __forceinline__ float ex2(float x) {
    float y; asm("ex2.approx.f32 %0,%1;" : "=f"(y) : "f"(x)); return y;
}
__device__ __forceinline__ uint32_t h2bits(__half2 h) {
    uint32_t u; *(__half2*)&u = h; return u;
}

// ---------------------------------------------------------------------------
// Fused QKV projection: ONE kernel, x tile loaded once, 3 weight planes.
// grid (ND/PBN=2, NSEQ/PBM=256), 256 threads (8 warps, 2x4 warp grid).
// Per-output k-accumulation order matches the previous kernel exactly ->
// bit-identical Q/K/V.
// ---------------------------------------------------------------------------
__global__ __launch_bounds__(256, 1) void proj_qkv(
    const float* __restrict__ x,
    const float* __restrict__ Wq, const float* __restrict__ Wk,
    const float* __restrict__ Wv,
    __half* __restrict__ Qh, __half* __restrict__ Kh, __half* __restrict__ Vh)
{
    extern __shared__ char sm[];
    const int K = ND;
    const int t = threadIdx.x, lane = t & 31, wid = t >> 5;
    const int wm = wid >> 2, wn = wid & 3;          // 2 x 4 warp grid, 32x32
    const int row0 = blockIdx.y * PBM, col0 = blockIdx.x * PBN;
    const uint32_t smb = s2u(sm);

    const float* W[3] = {Wq, Wk, Wv};
    __half* Cout[3] = {Qh, Kh, Vh};

    // loader indices
    const int xr = t >> 2, xc = (t & 3) * 8;        // x tile [64][32]
    const int wr = t >> 1, wc = (t & 1) * 16;       // W tile [128][32]

    float4 rx[2], rw[3][4];
    float acc[3][2][4][4];
    #pragma unroll
    for (int z = 0; z < 3; z++)
        #pragma unroll
        for (int mi = 0; mi < 2; mi++)
            #pragma unroll
            for (int j = 0; j < 4; j++)
                #pragma unroll
                for (int e = 0; e < 4; e++) acc[z][mi][j][e] = 0.f;

    auto gload = [&](int kt) {
        const float* xp = x + (size_t)(row0 + xr) * K + kt * PBK + xc;
        rx[0] = *(const float4*)(xp);
        rx[1] = *(const float4*)(xp + 4);
        #pragma unroll
        for (int z = 0; z < 3; z++) {
            const float* wp = W[z] + (size_t)(col0 + wr) * K + kt * PBK + wc;
            #pragma unroll
            for (int i = 0; i < 4; i++) rw[z][i] = *(const float4*)(wp + 4 * i);
        }
    };
    auto sstore = [&](int buf) {
        char* s0 = sm + buf * P_STG;
        #pragma unroll
        for (int i = 0; i < 2; i++) {
            uint2 h;
            h.x = h2bits(__floats2half2_rn(rx[i].x, rx[i].y));
            h.y = h2bits(__floats2half2_rn(rx[i].z, rx[i].w));
            *(uint2*)(s0 + OFF_X + (xr * A_PAD + xc + 4 * i) * 2) = h;
        }
        #pragma unroll
        for (int z = 0; z < 3; z++)
            #pragma unroll
            for (int i = 0; i < 4; i++) {
                uint2 h;
                h.x = h2bits(__floats2half2_rn(rw[z][i].x, rw[z][i].y));
                h.y = h2bits(__floats2half2_rn(rw[z][i].z, rw[z][i].w));
                *(uint2*)(s0 + OFF_W + z * W_PL + (wr * A_PAD + wc + 4 * i) * 2) = h;
            }
    };
    auto compute = [&](int buf) {
        uint32_t sb = smb + buf * P_STG;
        #pragma unroll
        for (int ks = 0; ks < 2; ks++) {
            const int col = ks * 16 + (lane >> 4) * 8;
            uint32_t ah[2][4];
            #pragma unroll
            for (int mi = 0; mi < 2; mi++) {
                int row = wm * 32 + mi * 16 + (lane & 15);
                ldm4(ah[mi], sb + OFF_X + (uint32_t)(row * A_PAD + col) * 2);
            }
            #pragma unroll
            for (int z = 0; z < 3; z++) {
                uint32_t bh[2][4];
                #pragma unroll
                for (int ni = 0; ni < 2; ni++) {
                    int row = wn * 32 + ni * 16 + (lane & 15);
                    ldm4(bh[ni], sb + OFF_W + z * W_PL
                                  + (uint32_t)(row * A_PAD + col) * 2);
                }
                #pragma unroll
                for (int mi = 0; mi < 2; mi++)
                    #pragma unroll
                    for (int j = 0; j < 4; j++) {
                        int ni = j >> 1, sbb = j & 1;
                        mma_f16(acc[z][mi][j], ah[mi],
                                bh[ni][sbb], bh[ni][sbb + 2]);
                    }
            }
        }
    };

    const int KT = K / PBK;
    gload(0); sstore(0); __syncthreads();
    for (int kt = 0; kt < KT; kt++) {
        if (kt + 1 < KT) gload(kt + 1);
        compute(kt & 1);
        __syncthreads();
        if (kt + 1 < KT) { sstore((kt + 1) & 1); __syncthreads(); }
    }

    // epilogue
    #pragma unroll
    for (int z = 0; z < 3; z++) {
        const float scale = (z == 0) ? QSCALE : 1.0f;
        __half* Ch = Cout[z];
        #pragma unroll
        for (int mi = 0; mi < 2; mi++)
            #pragma unroll
            for (int j = 0; j < 4; j++) {
                const float* c = acc[z][mi][j];
                int r  = row0 + wm * 32 + mi * 16 + (lane >> 2);
                int cc = col0 + wn * 32 + j * 8 + (lane & 3) * 2;
                #pragma unroll
                for (int hrow = 0; hrow < 2; hrow++) {
                    float v0 = c[hrow * 2 + 0] * scale;
                    float v1 = c[hrow * 2 + 1] * scale;
                    size_t idx = (size_t)(r + hrow * 8) * ND + cc;
                    *(uint32_t*)&Ch[idx] = h2bits(__floats2half2_rn(v0, v1));
                }
            }
    }
}

// ---------------------------------------------------------------------------
// Fused flash attention (R15 structure) + de-phase spin: odd CTAs delay
// ~half an iteration so co-resident CTA pairs interleave their MMA and
// scalar/barrier phases instead of phase-locking.
// ---------------------------------------------------------------------------
__global__ __launch_bounds__(FTH, 2) void flash(
    const __half* __restrict__ Qh, const __half* __restrict__ Kh,
    const __half* __restrict__ Vh, float* __restrict__ O)
{
    extern __shared__ char sm[];
    const uint32_t smb = s2u(sm);
    const int t = threadIdx.x, lane = t & 31, w = t >> 5;
    const int b = blockIdx.y, q0 = blockIdx.x * QR;

    const size_t qbase = ((size_t)b * NS + q0) * ND;
    const size_t kvb   = (size_t)b * NS * ND;

    auto loadQ = [&]() {
        for (int i = t; i < QR * 32; i += FTH) {
            int r = i >> 5, ch = i & 31;
            cp16(smb + F_QH + (uint32_t)(r * PAD * 2 + ch * 16),
                 Qh + qbase + (size_t)r * ND + ch * 8);
        }
    };
    auto loadKV = [&](int blk, int st) {
        size_t base = kvb + (size_t)blk * KC * ND;
        uint32_t kb = smb + (st ? F_K1 : F_K0);
        uint32_t vb = smb + (st ? F_V1 : F_V0);
        for (int i = t; i < KC * 32; i += FTH) {
            int r = i >> 5, ch = i & 31;
            uint32_t d = (uint32_t)(r * PAD * 2 + ch * 16);
            cp16(kb + d, Kh + base + (size_t)r * ND + ch * 8);
            cp16(vb + d, Vh + base + (size_t)r * ND + ch * 8);
        }
    };

    loadQ(); loadKV(0, 0); cp_commit();

    // De-phase: odd CTAs wait ~half an iteration once. Output-invariant.
    if ((blockIdx.x ^ blockIdx.y) & 1) {
        long long t0 = clock64();
        while (clock64() - t0 < 1800) { }
    }

    float o[32][4];
    #pragma unroll
    for (int g = 0; g < 32; g++)
        #pragma unroll
        for (int e = 0; e < 4; e++) o[g][e] = 0.f;
    float lsum0 = 0.f, lsum1 = 0.f;

    const uint32_t qrow_off  = (uint32_t)((w * 16 + (lane & 15)) * PAD) * 2;
    const uint32_t row0_off  = (uint32_t)((lane & 15) * PAD) * 2;
    const uint32_t row1_off  = (uint32_t)((16 + (lane & 15)) * PAD) * 2;
    const uint32_t fcol_off  = (uint32_t)((lane >> 4) * 8) * 2;

    for (int blk = 0; blk < NBLK; blk++) {
        const int st = blk & 1;

        cp_wait<0>();
        __syncthreads();
        if (blk + 1 < NBLK) { loadKV(blk + 1, st ^ 1); cp_commit(); }

        const uint32_t kbase = smb + (st ? F_K1 : F_K0) + fcol_off;
        const uint32_t vbase = smb + (st ? F_V1 : F_V0) + fcol_off;
        const uint32_t qb    = smb + F_QH + qrow_off + fcol_off;

        // ---- QK^T (both key halves), distance-2 fragment prefetch ----
        float s[4][4];
        #pragma unroll
        for (int nj = 0; nj < 4; nj++)
            #pragma unroll
            for (int e = 0; e < 4; e++) s[nj][e] = 0.f;

        uint32_t qf[3][4], kf0[3][4], kf1[3][4];
        ldm4(qf[0],  qb);
        ldm4(kf0[0], kbase + row0_off);
        ldm4(kf1[0], kbase + row1_off);
        ldm4(qf[1],  qb + 32);
        ldm4(kf0[1], kbase + row0_off + 32);
        ldm4(kf1[1], kbase + row1_off + 32);
        #pragma unroll
        for (int k16 = 0; k16 < 16; k16++) {
            const int cur = k16 % 3;
            if (k16 < 14) {
                const int nl = (k16 + 2) % 3;
                const uint32_t c = (uint32_t)((k16 + 2) * 16) * 2;
                ldm4(qf[nl],  qb + c);
                ldm4(kf0[nl], kbase + row0_off + c);
                ldm4(kf1[nl], kbase + row1_off + c);
            }
            mma_f16(s[0], qf[cur], kf0[cur][0], kf0[cur][2]);
            mma_f16(s[1], qf[cur], kf0[cur][1], kf0[cur][3]);
            mma_f16(s[2], qf[cur], kf1[cur][0], kf1[cur][2]);
            mma_f16(s[3], qf[cur], kf1[cur][1], kf1[cur][3]);
        }

        uint32_t pah[2][4];

        // ---- preload PV-A frags, then convertA ----
        uint32_t vfa[3][4];
        ldm4t(vfa[0], vbase + row0_off);
        ldm4t(vfa[1], vbase + row0_off + 32);
        {
            s[0][0] = ex2(s[0][0]); lsum0 += s[0][0];
            s[0][1] = ex2(s[0][1]); lsum0 += s[0][1];
            s[0][2] = ex2(s[0][2]); lsum1 += s[0][2];
            s[0][3] = ex2(s[0][3]); lsum1 += s[0][3];
            s[1][0] = ex2(s[1][0]); lsum0 += s[1][0];
            s[1][1] = ex2(s[1][1]); lsum0 += s[1][1];
            s[1][2] = ex2(s[1][2]); lsum1 += s[1][2];
            s[1][3] = ex2(s[1][3]); lsum1 += s[1][3];
            pah[0][0] = h2bits(__floats2half2_rn(s[0][0], s[0][1]));
            pah[0][1] = h2bits(__floats2half2_rn(s[0][2], s[0][3]));
            pah[0][2] = h2bits(__floats2half2_rn(s[1][0], s[1][1]));
            pah[0][3] = h2bits(__floats2half2_rn(s[1][2], s[1][3]));
        }

        // ---- PV-A ----
        #pragma unroll
        for (int g = 0; g < 16; g++) {
            const int cur = g % 3;
            if (g < 14) {
                const int nl = (g + 2) % 3;
                ldm4t(vfa[nl], vbase + row0_off + (uint32_t)((g + 2) * 16) * 2);
            }
            mma_f16(o[g * 2 + 0], pah[0], vfa[cur][0], vfa[cur][1]);
            mma_f16(o[g * 2 + 1], pah[0], vfa[cur][2], vfa[cur][3]);
        }

        // ---- preload PV-B frags, then convertB ----
        uint32_t vfb[3][4];
        ldm4t(vfb[0], vbase + row1_off);
        ldm4t(vfb[1], vbase + row1_off + 32);
        {
            s[2][0] = ex2(s[2][0]); lsum0 += s[2][0];
            s[2][1] = ex2(s[2][1]); lsum0 += s[2][1];
            s[2][2] = ex2(s[2][2]); lsum1 += s[2][2];
            s[2][3] = ex2(s[2][3]); lsum1 += s[2][3];
            s[3][0] = ex2(s[3][0]); lsum0 += s[3][0];
            s[3][1] = ex2(s[3][1]); lsum0 += s[3][1];
            s[3][2] = ex2(s[3][2]); lsum1 += s[3][2];
            s[3][3] = ex2(s[3][3]); lsum1 += s[3][3];
            pah[1][0] = h2bits(__floats2half2_rn(s[2][0], s[2][1]));
            pah[1][1] = h2bits(__floats2half2_rn(s[2][2], s[2][3]));
            pah[1][2] = h2bits(__floats2half2_rn(s[3][0], s[3][1]));
            pah[1][3] = h2bits(__floats2half2_rn(s[3][2], s[3][3]));
        }

        // ---- PV-B ----
        #pragma unroll
        for (int g = 0; g < 16; g++) {
            const int cur = g % 3;
            if (g < 14) {
                const int nl = (g + 2) % 3;
                ldm4t(vfb[nl], vbase + row1_off + (uint32_t)((g + 2) * 16) * 2);
            }
            mma_f16(o[g * 2 + 0], pah[1], vfb[cur][0], vfb[cur][1]);
            mma_f16(o[g * 2 + 1], pah[1], vfb[cur][2], vfb[cur][3]);
        }
    }

    // ---- epilogue: reduce row sums across the lane quad, O /= l ----
    lsum0 += __shfl_xor_sync(0xffffffffu, lsum0, 1);
    lsum0 += __shfl_xor_sync(0xffffffffu, lsum0, 2);
    lsum1 += __shfl_xor_sync(0xffffffffu, lsum1, 1);
    lsum1 += __shfl_xor_sync(0xffffffffu, lsum1, 2);
    const float r0 = 1.f / lsum0, r1 = 1.f / lsum1;
    const int orow = q0 + w * 16 + (lane >> 2);
    const int ocol = (lane & 3) * 2;
    float* ob = O + ((size_t)b * NS) * ND;
    #pragma unroll
    for (int g = 0; g < 32; g++) {
        int cc = g * 8 + ocol;
        float2 v0 = {o[g][0] * r0, o[g][1] * r0};
        float2 v1 = {o[g][2] * r1, o[g][3] * r1};
        *(float2*)&ob[(size_t)orow * ND + cc]       = v0;
        *(float2*)&ob[(size_t)(orow + 8) * ND + cc] = v1;
    }
}

// ---------------------------------------------------------------------------
// Launch
// ---------------------------------------------------------------------------
extern "C" void kernel_launch(void* const* d_in, const int* in_sizes, int n_in,
                              void* d_out, int out_size)
{
    const float* x  = (const float*)d_in[0];
    const float* Wq = (const float*)d_in[1];
    const float* Wk = (const float*)d_in[2];
    const float* Wv = (const float*)d_in[3];
    float* out = (float*)d_out;

    __half *qh, *kh, *vh;
    cudaGetSymbolAddress((void**)&qh, g_qh);
    cudaGetSymbolAddress((void**)&kh, g_kh);
    cudaGetSymbolAddress((void**)&vh, g_vh);

    cudaFuncSetAttribute(proj_qkv, cudaFuncAttributeMaxDynamicSharedMemorySize, P_SMEM);
    cudaFuncSetAttribute(flash,    cudaFuncAttributeMaxDynamicSharedMemorySize, F_SMEM);

    {
        dim3 g(ND / PBN, NSEQ / PBM);
        proj_qkv<<<g, 256, P_SMEM>>>(x, Wq, Wk, Wv, qh, kh, vh);
    }
    {
        dim3 g(NS / QR, NB);
        flash<<<g, FTH, F_SMEM>>>(qh, kh, vh, out);
    }
}